// round 12
// baseline (speedup 1.0000x reference)
#include <cuda_runtime.h>
#include <math.h>

#define NA 10000
#define NE 500000
#define NSPEC 119
#define NPAIR (NSPEC*NSPEC)      // 14161
#define EMBSTRIDE 40             // padded from 35, 160B = 16B aligned
#define NEMB (NPAIR*EMBSTRIDE)   // 566440
#define NFEAT 360
#define NMOM 100                 // 5*(1+3+6+10)

// Scratch (no allocations allowed -> device globals; zero-init at module load)
__device__ int    g_count[NA];        // per-atom histogram
__device__ int    g_off[NA + 1];
__device__ int    g_cursor[NA];
__device__ int    g_pcount[NPAIR];    // per-pair histogram
__device__ int    g_poff[NPAIR + 1];
__device__ int    g_pcursor[NPAIR];
__device__ int    g_epair[NE];        // pair id per edge
__device__ float  g_emb[NEMB];
__device__ float4 g_pdata[NE];        // pair-sorted: {x,y,z,bitcast(pos_atom)}
__device__ float4 g_edata[NE * 2];    // atom-sorted: {r0..r3},{r4,dnx,dny,dnz}

// ---------------------------------------------------------------------------
// Prep + both histograms. g_count zeroed by k_atomf, g_pcount by k_edge (and
// statically zero-initialized for the first run).
// ---------------------------------------------------------------------------
__global__ void k_prep_hist(const float* __restrict__ emb,
                            const int* __restrict__ nbr,
                            const int* __restrict__ Z) {
    int i = blockIdx.x * blockDim.x + threadIdx.x;
    if (i < NEMB) {
        int pair = i / EMBSTRIDE;
        int slot = i - pair * EMBSTRIDE;
        float scale = powf(2.0f * (49.0f / 36.0f) / 3.14159265358979f, 0.75f) * rsqrtf(7.0f);
        g_emb[i] = (slot < 35) ? emb[pair * 35 + slot] * scale : 0.0f;
    }
    if (i < NE) {
        int ii = __ldg(nbr + i);
        int jj = __ldg(nbr + NE + i);
        int pair = __ldg(Z + ii) * NSPEC + __ldg(Z + jj);
        g_epair[i] = pair;
        atomicAdd(&g_count[jj], 1);
        atomicAdd(&g_pcount[pair], 1);
    }
}

// ---------------------------------------------------------------------------
// Two independent single-block scans (atoms, pairs) in one kernel launch.
// ---------------------------------------------------------------------------
template <int CH, int N>
__device__ void scan_block(const int* __restrict__ cnt, int* off, int* cur) {
    __shared__ int sh[1024];
    int t = threadIdx.x;
    int loc[CH];
    int sum = 0;
#pragma unroll
    for (int c = 0; c < CH; c++) {
        int idx = t * CH + c;
        loc[c] = sum;
        sum += (idx < N) ? cnt[idx] : 0;
    }
    sh[t] = sum;
    __syncthreads();
    for (int o = 1; o < 1024; o <<= 1) {
        int v = (t >= o) ? sh[t - o] : 0;
        __syncthreads();
        sh[t] += v;
        __syncthreads();
    }
    int exc = (t > 0) ? sh[t - 1] : 0;
#pragma unroll
    for (int c = 0; c < CH; c++) {
        int idx = t * CH + c;
        if (idx < N) {
            int o2 = exc + loc[c];
            off[idx] = o2;
            cur[idx] = o2;
        }
    }
    if (t == 1023) off[N] = sh[1023];
}

__global__ void k_scan2() {
    if (blockIdx.x == 0) scan_block<10, NA>(g_count, g_off, g_cursor);
    else                 scan_block<14, NPAIR>(g_pcount, g_poff, g_pcursor);
}

// ---------------------------------------------------------------------------
// Scatter: pack {x,y,z,pos_atom} into pair-sorted order. Coalesced reads,
// one scattered 16B store per edge.
// ---------------------------------------------------------------------------
__global__ void __launch_bounds__(256) k_scatter(const float* __restrict__ drv,
                                                 const int* __restrict__ nbr) {
    __shared__ float s_xyz[768];
    int tid = threadIdx.x;
    int e = blockIdx.x * 256 + tid;
    int base3 = blockIdx.x * 768;
#pragma unroll
    for (int k = 0; k < 3; k++) {
        int idx = k * 256 + tid;
        if (base3 + idx < NE * 3) s_xyz[idx] = drv[base3 + idx];
    }
    __syncthreads();
    if (e >= NE) return;

    int pair = g_epair[e];
    int jj = __ldg(nbr + NE + e);
    int pos_p = atomicAdd(&g_pcursor[pair], 1);
    int pos_a = atomicAdd(&g_cursor[jj], 1);
    g_pdata[pos_p] = make_float4(s_xyz[3 * tid + 0], s_xyz[3 * tid + 1],
                                 s_xyz[3 * tid + 2], __int_as_float(pos_a));
}

// ---------------------------------------------------------------------------
// Edge phase: ONE WARP PER PAIR. Coefficients loaded once per pair into smem
// (broadcast reads); edge data fully coalesced; only the final 2x16B
// g_edata store is scattered. Also re-zeroes g_pcount for next replay.
// ---------------------------------------------------------------------------
__global__ void __launch_bounds__(128) k_edge() {
    __shared__ float4 s_q4[4][9];

    const float BETTA = 1.36111111f;        // 49/36
    const float PIR   = 0.52359877559f;     // pi/6
    const float SH0   = 0.5f;
    const float DSH   = 0.78571428571f;     // 5.5/7

    int tid = threadIdx.x;
    int w = tid >> 5;
    int lane = tid & 31;
    int pair = blockIdx.x * 4 + w;

    // re-zero pair histogram for next run
    {
        int zi = blockIdx.x * 128 + tid;
        if (zi < NPAIR) g_pcount[zi] = 0;
    }
    if (pair >= NPAIR) return;

    int beg = g_poff[pair];
    int end = g_poff[pair + 1];
    if (beg == end) return;

    if (lane < 9) s_q4[w][lane] = *((const float4*)(g_emb + pair * EMBSTRIDE) + lane);
    __syncwarp();

    for (int p = beg + lane; p < end; p += 32) {
        float4 pd = g_pdata[p];
        float x = pd.x, y = pd.y, z = pd.z;
        int pos = __float_as_int(pd.w);

        float r2 = fmaxf(x * x + y * y + z * z, 1e-24f);
        float irt = rsqrtf(r2);
        float dr = r2 * irt;
        float inv = __fdividef(1.0f, dr + 1e-5f);
        float dnx = x * inv, dny = y * inv, dnz = z * inv;
        float cut = 0.5f * (__cosf(fminf(dr, 6.0f) * PIR) + 1.0f);

        float basis[7];
#pragma unroll
        for (int b = 0; b < 7; b++) {
            float d = dr - (SH0 + DSH * (float)b);
            basis[b] = cut * __expf(-BETTA * d * d);
        }

        float rad[5] = {0.f, 0.f, 0.f, 0.f, 0.f};
#pragma unroll
        for (int c = 0; c < 9; c++) {
            float4 v = s_q4[w][c];
            int s0 = 4 * c;
            { int s = s0 + 0; if (s < 35) rad[s / 7] += v.x * basis[s % 7]; }
            { int s = s0 + 1; if (s < 35) rad[s / 7] += v.y * basis[s % 7]; }
            { int s = s0 + 2; if (s < 35) rad[s / 7] += v.z * basis[s % 7]; }
            { int s = s0 + 3; if (s < 35) rad[s / 7] += v.w * basis[s % 7]; }
        }

        g_edata[2 * pos]     = make_float4(rad[0], rad[1], rad[2], rad[3]);
        g_edata[2 * pos + 1] = make_float4(rad[4], dnx, dny, dnz);
    }
}

// Symmetric index helpers (fold to constants after unroll)
__device__ __forceinline__ int s2i(int i, int j) {
    return (i >= j) ? (i * (i + 1) / 2 + j) : (j * (j + 1) / 2 + i);
}
__device__ __forceinline__ int s3i(int i, int j, int k) {
    int a = i > j ? i : j;
    int b = i > j ? j : i;
    int c;
    if (k >= a)      { c = b; b = a; a = k; }
    else if (k >= b) { c = b; b = k; }
    else             { c = k; }
    return a * (a + 1) * (a + 2) / 6 + b * (b + 1) / 2 + c;
}

// ---------------------------------------------------------------------------
// Fused moment + feature phase. 256 threads = 32 atoms x 8 lanes.
// Phase 1: INTERLEAVED edge split (8 lanes of an atom read adjacent 32B
//          records -> ~4x fewer L1 wavefronts than contiguous sub-ranges),
//          xor butterfly, moments to smem.
// Phase 2: warp 0 computes contractions once per atom (minimum issue work),
//          chunked smem transpose, all-thread coalesced flushes.
// Also re-zeroes g_count for next replay.
// ---------------------------------------------------------------------------
__global__ void __launch_bounds__(256) k_atomf(float* __restrict__ outbuf) {
    __shared__ float s_mom[NMOM * 33];    // 13.2 KB
    __shared__ float s_feat[200 * 33];    // 26.4 KB

    int t = threadIdx.x;        // 0..255
    int ai = t >> 3;            // local atom 0..31
    int oct = t & 7;
    int a0 = blockIdx.x * 32;
    int a = a0 + ai;

    // re-zero atom histogram for next run
    {
        int gi = blockIdx.x * 256 + t;
        if (gi < NA) g_count[gi] = 0;
    }

    float A0[5] = {0.f, 0.f, 0.f, 0.f, 0.f};
    float A1[5][3];
    float A2[5][6];
    float A3[5][10];
#pragma unroll
    for (int r = 0; r < 5; r++) {
#pragma unroll
        for (int u = 0; u < 3; u++) A1[r][u] = 0.f;
#pragma unroll
        for (int u = 0; u < 6; u++) A2[r][u] = 0.f;
#pragma unroll
        for (int u = 0; u < 10; u++) A3[r][u] = 0.f;
    }

    if (a < NA) {
        const int beg = g_off[a];
        const int end = g_off[a + 1];

#pragma unroll 2
        for (int p = beg + oct; p < end; p += 8) {
            float4 u0 = g_edata[2 * p];
            float4 u1 = g_edata[2 * p + 1];
            float radial[5] = {u0.x, u0.y, u0.z, u0.w, u1.x};
            float dnx = u1.y, dny = u1.z, dnz = u1.w;

            float g2[6] = {dnx * dnx, dny * dnx, dny * dny, dnz * dnx, dnz * dny, dnz * dnz};
            float g3[10] = {g2[0] * dnx, g2[1] * dnx, g2[2] * dnx, g2[2] * dny,
                            g2[3] * dnx, g2[4] * dnx, g2[4] * dny, g2[5] * dnx,
                            g2[5] * dny, g2[5] * dnz};
#pragma unroll
            for (int r = 0; r < 5; r++) {
                float s = radial[r];
                A0[r] += s;
                A1[r][0] += s * dnx;
                A1[r][1] += s * dny;
                A1[r][2] += s * dnz;
#pragma unroll
                for (int u = 0; u < 6; u++) A2[r][u] += s * g2[u];
#pragma unroll
                for (int u = 0; u < 10; u++) A3[r][u] += s * g3[u];
            }
        }
    }

    // Butterfly merge 8 lanes of each octet
#pragma unroll
    for (int d = 1; d <= 4; d <<= 1) {
#pragma unroll
        for (int r = 0; r < 5; r++) {
            A0[r] += __shfl_xor_sync(0xffffffffu, A0[r], d);
#pragma unroll
            for (int u = 0; u < 3; u++) A1[r][u] += __shfl_xor_sync(0xffffffffu, A1[r][u], d);
#pragma unroll
            for (int u = 0; u < 6; u++) A2[r][u] += __shfl_xor_sync(0xffffffffu, A2[r][u], d);
#pragma unroll
            for (int u = 0; u < 10; u++) A3[r][u] += __shfl_xor_sync(0xffffffffu, A3[r][u], d);
        }
    }

    if (oct == 0 && a < NA) {
#pragma unroll
        for (int r = 0; r < 5; r++) s_mom[r * 33 + ai] = A0[r];
#pragma unroll
        for (int r = 0; r < 5; r++)
#pragma unroll
            for (int u = 0; u < 3; u++) s_mom[(5 + r * 3 + u) * 33 + ai] = A1[r][u];
#pragma unroll
        for (int r = 0; r < 5; r++)
#pragma unroll
            for (int u = 0; u < 6; u++) s_mom[(20 + r * 6 + u) * 33 + ai] = A2[r][u];
#pragma unroll
        for (int r = 0; r < 5; r++)
#pragma unroll
            for (int u = 0; u < 10; u++) s_mom[(50 + r * 10 + u) * 33 + ai] = A3[r][u];
    }
    __syncthreads();

    int nat = NA - a0;
    if (nat > 32) nat = 32;

    // ---- Phase 2: warp 0, one thread per atom ----
    bool act = (t < 32) && (a0 + t < NA);

    float B0[5] = {0.f, 0.f, 0.f, 0.f, 0.f};
    float B1[5][3] = {};
    float B2[5][6] = {};
    float B3[5][10] = {};
    if (act) {
#pragma unroll
        for (int r = 0; r < 5; r++) B0[r] = s_mom[r * 33 + t];
#pragma unroll
        for (int r = 0; r < 5; r++)
#pragma unroll
            for (int u = 0; u < 3; u++) B1[r][u] = s_mom[(5 + r * 3 + u) * 33 + t];
#pragma unroll
        for (int r = 0; r < 5; r++)
#pragma unroll
            for (int u = 0; u < 6; u++) B2[r][u] = s_mom[(20 + r * 6 + u) * 33 + t];
#pragma unroll
        for (int r = 0; r < 5; r++)
#pragma unroll
            for (int u = 0; u < 10; u++) B3[r][u] = s_mom[(50 + r * 10 + u) * 33 + t];
    }

    int o = 0;
#define EMIT(v) do { if (act) s_feat[(o) * 33 + t] = (v); o++; } while (0)

    if (t < 32) {
        // ---- chunk A: c0..c5 (160 features) ----
#pragma unroll
        for (int r = 0; r < 5; r++) EMIT(B0[r]);

#pragma unroll
        for (int r = 0; r < 5; r++)
#pragma unroll
            for (int s = 0; s <= r; s++) {
                float v = 0.f;
#pragma unroll
                for (int i = 0; i < 3; i++) v += B1[r][i] * B1[s][i];
                EMIT(v);
            }

        {
            const float W2[6] = {1.f, 2.f, 1.f, 2.f, 2.f, 1.f};
#pragma unroll
            for (int r = 0; r < 5; r++)
#pragma unroll
                for (int s = 0; s <= r; s++) {
                    float v = 0.f;
#pragma unroll
                    for (int u = 0; u < 6; u++) v += W2[u] * B2[r][u] * B2[s][u];
                    EMIT(v);
                }
        }

        {
            const float W3[10] = {1.f, 3.f, 3.f, 1.f, 3.f, 6.f, 3.f, 3.f, 3.f, 1.f};
#pragma unroll
            for (int r = 0; r < 5; r++)
#pragma unroll
                for (int s = 0; s <= r; s++) {
                    float v = 0.f;
#pragma unroll
                    for (int u = 0; u < 10; u++) v += W3[u] * B3[r][u] * B3[s][u];
                    EMIT(v);
                }
        }

        // c4
#pragma unroll
        for (int r = 0; r < 5; r++)
#pragma unroll
            for (int s = 0; s <= r; s++)
#pragma unroll
                for (int tt = 0; tt <= s; tt++) {
                    float v = 0.f;
#pragma unroll
                    for (int i = 0; i < 3; i++)
#pragma unroll
                        for (int j = 0; j < 3; j++)
#pragma unroll
                            for (int k = 0; k < 3; k++)
                                v += B2[r][s2i(i, j)] * B2[s][s2i(i, k)] * B2[tt][s2i(j, k)];
                    EMIT(v);
                }

        // c5
#pragma unroll
        for (int r = 0; r < 5; r++)
#pragma unroll
            for (int s = 0; s <= r; s++)
#pragma unroll
                for (int tt = 0; tt < 5; tt++) {
                    float v = 0.f;
#pragma unroll
                    for (int i = 0; i < 3; i++)
#pragma unroll
                        for (int j = 0; j < 3; j++)
                            v += B1[r][i] * B1[s][j] * B2[tt][s2i(i, j)];
                    EMIT(v);
                }
    }

    // flush chunk A: features [0,160)
    __syncthreads();
    for (int idx = t; idx < nat * 160; idx += 256) {
        int i = idx / 160;
        int f = idx - i * 160;
        outbuf[(size_t)(a0 + i) * NFEAT + f] = s_feat[f * 33 + i];
    }
    __syncthreads();

    o = 0;
    if (t < 32) {
        // ---- chunk B: c6, c7 (200 features) ----
#pragma unroll
        for (int r = 0; r < 5; r++)
#pragma unroll
            for (int s = 0; s <= r; s++) {
                float B[9];
#pragma unroll
                for (int k = 0; k < 3; k++)
#pragma unroll
                    for (int l = 0; l < 3; l++) {
                        float u = 0.f;
#pragma unroll
                        for (int i = 0; i < 3; i++)
#pragma unroll
                            for (int j = 0; j < 3; j++)
                                u += B3[r][s3i(i, j, k)] * B3[s][s3i(i, j, l)];
                        B[k * 3 + l] = u;
                    }
#pragma unroll
                for (int tt = 0; tt < 5; tt++) {
                    float v = 0.f;
#pragma unroll
                    for (int k = 0; k < 3; k++)
#pragma unroll
                        for (int l = 0; l < 3; l++)
                            v += B[k * 3 + l] * B2[tt][s2i(k, l)];
                    EMIT(v);
                }
            }

#pragma unroll
        for (int r = 0; r < 5; r++)
#pragma unroll
            for (int s = 0; s < 5; s++) {
                float C[3];
#pragma unroll
                for (int k = 0; k < 3; k++) {
                    float u = 0.f;
#pragma unroll
                    for (int i = 0; i < 3; i++)
#pragma unroll
                        for (int j = 0; j < 3; j++)
                            u += B3[r][s3i(i, j, k)] * B2[s][s2i(i, j)];
                    C[k] = u;
                }
#pragma unroll
                for (int tt = 0; tt < 5; tt++) {
                    float v = 0.f;
#pragma unroll
                    for (int k = 0; k < 3; k++) v += C[k] * B1[tt][k];
                    EMIT(v);
                }
            }
    }
#undef EMIT

    // flush chunk B: features [160,360)
    __syncthreads();
    for (int idx = t; idx < nat * 200; idx += 256) {
        int i = idx / 200;
        int f = idx - i * 200;
        outbuf[(size_t)(a0 + i) * NFEAT + 160 + f] = s_feat[f * 33 + i];
    }
}

extern "C" void kernel_launch(void* const* d_in, const int* in_sizes, int n_in,
                              void* d_out, int out_size) {
    const float* dr_vec = (const float*)d_in[0];
    const int*   Z      = (const int*)d_in[1];
    const int*   nbr    = (const int*)d_in[2];
    const float* emb    = (const float*)d_in[3];
    float*       out    = (float*)d_out;

    k_prep_hist<<<(NEMB + 255) / 256, 256>>>(emb, nbr, Z);
    k_scan2<<<2, 1024>>>();
    k_scatter<<<(NE + 255) / 256, 256>>>(dr_vec, nbr);
    k_edge<<<(NPAIR + 3) / 4, 128>>>();
    k_atomf<<<(NA + 31) / 32, 256>>>(out);
}

// round 14
// speedup vs baseline: 1.3181x; 1.3181x over previous
#include <cuda_runtime.h>
#include <math.h>

#define NA 10000
#define NE 500000
#define NSPEC 119
#define NPAIR (NSPEC*NSPEC)      // 14161
#define EMBSTRIDE 40             // padded from 35, 160B = 16B aligned
#define NEMB (NPAIR*EMBSTRIDE)   // 566440
#define NFEAT 360
#define NMOM 100                 // 5*(1+3+6+10)

// Scratch (no allocations allowed -> device globals; zero-init at module load)
__device__ int    g_count[NA];        // per-atom histogram
__device__ int    g_off[NA + 1];
__device__ int    g_pcount[NPAIR];    // per-pair histogram
__device__ int    g_poff[NPAIR + 1];
__device__ int    g_epair[NE];        // pair id per edge
__device__ int    g_rank[NE];         // rank within atom segment
__device__ int    g_prank[NE];        // rank within pair segment
__device__ float  g_emb[NEMB];
__device__ float4 g_pdata[NE];        // pair-sorted: {x,y,z,bitcast(pos_atom)}
__device__ float4 g_edata[NE * 2];    // atom-sorted: {r0..r3},{r4,dnx,dny,dnz}
__device__ float  g_mom[NMOM * NA];   // transposed moments [comp][atom]

// ---------------------------------------------------------------------------
// Prep + both histograms. The atomicAdd return value IS the within-segment
// rank -> scatter needs no atomics. g_count zeroed by k_mom, g_pcount by
// k_edge (and statically zero-initialized for the first run).
// ---------------------------------------------------------------------------
__global__ void k_prep_hist(const float* __restrict__ emb,
                            const int* __restrict__ nbr,
                            const int* __restrict__ Z) {
    int i = blockIdx.x * blockDim.x + threadIdx.x;
    if (i < NEMB) {
        int pair = i / EMBSTRIDE;
        int slot = i - pair * EMBSTRIDE;
        float scale = powf(2.0f * (49.0f / 36.0f) / 3.14159265358979f, 0.75f) * rsqrtf(7.0f);
        g_emb[i] = (slot < 35) ? emb[pair * 35 + slot] * scale : 0.0f;
    }
    if (i < NE) {
        int ii = __ldg(nbr + i);
        int jj = __ldg(nbr + NE + i);
        int pair = __ldg(Z + ii) * NSPEC + __ldg(Z + jj);
        g_epair[i] = pair;
        g_rank[i]  = atomicAdd(&g_count[jj], 1);
        g_prank[i] = atomicAdd(&g_pcount[pair], 1);
    }
}

// ---------------------------------------------------------------------------
// Two independent single-block scans (atoms, pairs) in one kernel launch.
// ---------------------------------------------------------------------------
template <int CH, int N>
__device__ void scan_block(const int* __restrict__ cnt, int* off) {
    __shared__ int sh[1024];
    int t = threadIdx.x;
    int loc[CH];
    int sum = 0;
#pragma unroll
    for (int c = 0; c < CH; c++) {
        int idx = t * CH + c;
        loc[c] = sum;
        sum += (idx < N) ? cnt[idx] : 0;
    }
    sh[t] = sum;
    __syncthreads();
    for (int o = 1; o < 1024; o <<= 1) {
        int v = (t >= o) ? sh[t - o] : 0;
        __syncthreads();
        sh[t] += v;
        __syncthreads();
    }
    int exc = (t > 0) ? sh[t - 1] : 0;
#pragma unroll
    for (int c = 0; c < CH; c++) {
        int idx = t * CH + c;
        if (idx < N) off[idx] = exc + loc[c];
    }
    if (t == 1023) off[N] = sh[1023];
}

__global__ void k_scan2() {
    if (blockIdx.x == 0) scan_block<10, NA>(g_count, g_off);
    else                 scan_block<14, NPAIR>(g_pcount, g_poff);
}

// ---------------------------------------------------------------------------
// Scatter: atomic-free (pos = off + rank). Pure gather + one scattered 16B
// store per edge.
// ---------------------------------------------------------------------------
__global__ void __launch_bounds__(256) k_scatter(const float* __restrict__ drv,
                                                 const int* __restrict__ nbr) {
    __shared__ float s_xyz[768];
    int tid = threadIdx.x;
    int e = blockIdx.x * 256 + tid;
    int base3 = blockIdx.x * 768;
#pragma unroll
    for (int k = 0; k < 3; k++) {
        int idx = k * 256 + tid;
        if (base3 + idx < NE * 3) s_xyz[idx] = drv[base3 + idx];
    }
    __syncthreads();
    if (e >= NE) return;

    int pair = g_epair[e];
    int jj = __ldg(nbr + NE + e);
    int pos_p = g_poff[pair] + g_prank[e];
    int pos_a = g_off[jj] + g_rank[e];
    g_pdata[pos_p] = make_float4(s_xyz[3 * tid + 0], s_xyz[3 * tid + 1],
                                 s_xyz[3 * tid + 2], __int_as_float(pos_a));
}

// ---------------------------------------------------------------------------
// Edge phase: ONE WARP PER PAIR. Coefficients loaded once per pair into smem
// (broadcast reads); edge data fully coalesced; only the final 2x16B
// g_edata store is scattered. Also re-zeroes g_pcount for next replay.
// ---------------------------------------------------------------------------
__global__ void __launch_bounds__(128) k_edge() {
    __shared__ float4 s_q4[4][9];

    const float BETTA = 1.36111111f;        // 49/36
    const float PIR   = 0.52359877559f;     // pi/6
    const float SH0   = 0.5f;
    const float DSH   = 0.78571428571f;     // 5.5/7

    int tid = threadIdx.x;
    int w = tid >> 5;
    int lane = tid & 31;
    int pair = blockIdx.x * 4 + w;

    // re-zero pair histogram for next run
    {
        int zi = blockIdx.x * 128 + tid;
        if (zi < NPAIR) g_pcount[zi] = 0;
    }
    if (pair >= NPAIR) return;

    int beg = g_poff[pair];
    int end = g_poff[pair + 1];
    if (beg == end) return;

    if (lane < 9) s_q4[w][lane] = *((const float4*)(g_emb + pair * EMBSTRIDE) + lane);
    __syncwarp();

    for (int p = beg + lane; p < end; p += 32) {
        float4 pd = g_pdata[p];
        float x = pd.x, y = pd.y, z = pd.z;
        int pos = __float_as_int(pd.w);

        float r2 = fmaxf(x * x + y * y + z * z, 1e-24f);
        float irt = rsqrtf(r2);
        float dr = r2 * irt;
        float inv = __fdividef(1.0f, dr + 1e-5f);
        float dnx = x * inv, dny = y * inv, dnz = z * inv;
        float cut = 0.5f * (__cosf(fminf(dr, 6.0f) * PIR) + 1.0f);

        float basis[7];
#pragma unroll
        for (int b = 0; b < 7; b++) {
            float d = dr - (SH0 + DSH * (float)b);
            basis[b] = cut * __expf(-BETTA * d * d);
        }

        float rad[5] = {0.f, 0.f, 0.f, 0.f, 0.f};
#pragma unroll
        for (int c = 0; c < 9; c++) {
            float4 v = s_q4[w][c];
            int s0 = 4 * c;
            { int s = s0 + 0; if (s < 35) rad[s / 7] += v.x * basis[s % 7]; }
            { int s = s0 + 1; if (s < 35) rad[s / 7] += v.y * basis[s % 7]; }
            { int s = s0 + 2; if (s < 35) rad[s / 7] += v.z * basis[s % 7]; }
            { int s = s0 + 3; if (s < 35) rad[s / 7] += v.w * basis[s % 7]; }
        }

        g_edata[2 * pos]     = make_float4(rad[0], rad[1], rad[2], rad[3]);
        g_edata[2 * pos + 1] = make_float4(rad[4], dnx, dny, dnz);
    }
}

// Symmetric index helpers (fold to constants after unroll)
__device__ __forceinline__ int s2i(int i, int j) {
    return (i >= j) ? (i * (i + 1) / 2 + j) : (j * (j + 1) / 2 + i);
}
__device__ __forceinline__ int s3i(int i, int j, int k) {
    int a = i > j ? i : j;
    int b = i > j ? j : i;
    int c;
    if (k >= a)      { c = b; b = a; a = k; }
    else if (k >= b) { c = b; b = k; }
    else             { c = k; }
    return a * (a + 1) * (a + 2) / 6 + b * (b + 1) / 2 + c;
}

// ---------------------------------------------------------------------------
// Moment phase: eight threads per atom with INTERLEAVED edge split (an
// atom's 8 lanes read adjacent 32B records -> ~8 lines/warp-instr instead of
// ~32), xor-1/2/4 butterfly, octet-lane-0 stores 100 floats transposed.
// Also re-zeroes g_count for next replay.
// ---------------------------------------------------------------------------
__global__ void __launch_bounds__(128) k_mom() {
    int t = threadIdx.x;
    int ai = t >> 3;
    int oct = t & 7;
    int a = blockIdx.x * 16 + ai;

    {
        int gi = blockIdx.x * 128 + t;
        if (gi < NA) g_count[gi] = 0;
    }

    float A0[5] = {0.f, 0.f, 0.f, 0.f, 0.f};
    float A1[5][3];
    float A2[5][6];
    float A3[5][10];
#pragma unroll
    for (int r = 0; r < 5; r++) {
#pragma unroll
        for (int u = 0; u < 3; u++) A1[r][u] = 0.f;
#pragma unroll
        for (int u = 0; u < 6; u++) A2[r][u] = 0.f;
#pragma unroll
        for (int u = 0; u < 10; u++) A3[r][u] = 0.f;
    }

    if (a < NA) {
        const int beg = g_off[a];
        const int end = g_off[a + 1];

#pragma unroll 2
        for (int p = beg + oct; p < end; p += 8) {
            float4 u0 = g_edata[2 * p];
            float4 u1 = g_edata[2 * p + 1];
            float radial[5] = {u0.x, u0.y, u0.z, u0.w, u1.x};
            float dnx = u1.y, dny = u1.z, dnz = u1.w;

            float g2[6] = {dnx * dnx, dny * dnx, dny * dny, dnz * dnx, dnz * dny, dnz * dnz};
            float g3[10] = {g2[0] * dnx, g2[1] * dnx, g2[2] * dnx, g2[2] * dny,
                            g2[3] * dnx, g2[4] * dnx, g2[4] * dny, g2[5] * dnx,
                            g2[5] * dny, g2[5] * dnz};
#pragma unroll
            for (int r = 0; r < 5; r++) {
                float s = radial[r];
                A0[r] += s;
                A1[r][0] += s * dnx;
                A1[r][1] += s * dny;
                A1[r][2] += s * dnz;
#pragma unroll
                for (int u = 0; u < 6; u++) A2[r][u] += s * g2[u];
#pragma unroll
                for (int u = 0; u < 10; u++) A3[r][u] += s * g3[u];
            }
        }
    }

#pragma unroll
    for (int d = 1; d <= 4; d <<= 1) {
#pragma unroll
        for (int r = 0; r < 5; r++) {
            A0[r] += __shfl_xor_sync(0xffffffffu, A0[r], d);
#pragma unroll
            for (int u = 0; u < 3; u++) A1[r][u] += __shfl_xor_sync(0xffffffffu, A1[r][u], d);
#pragma unroll
            for (int u = 0; u < 6; u++) A2[r][u] += __shfl_xor_sync(0xffffffffu, A2[r][u], d);
#pragma unroll
            for (int u = 0; u < 10; u++) A3[r][u] += __shfl_xor_sync(0xffffffffu, A3[r][u], d);
        }
    }

    if (oct == 0 && a < NA) {
#pragma unroll
        for (int r = 0; r < 5; r++) g_mom[r * NA + a] = A0[r];
#pragma unroll
        for (int r = 0; r < 5; r++)
#pragma unroll
            for (int u = 0; u < 3; u++) g_mom[(5 + r * 3 + u) * NA + a] = A1[r][u];
#pragma unroll
        for (int r = 0; r < 5; r++)
#pragma unroll
            for (int u = 0; u < 6; u++) g_mom[(20 + r * 6 + u) * NA + a] = A2[r][u];
#pragma unroll
        for (int r = 0; r < 5; r++)
#pragma unroll
            for (int u = 0; u < 10; u++) g_mom[(50 + r * 10 + u) * NA + a] = A3[r][u];
    }
}

// ---------------------------------------------------------------------------
// Feature phase: 64 threads per 32 atoms. Warp 0 computes chunk A (c0..c5,
// 160 feats); warp 1 CONCURRENTLY computes chunk B (c6,c7, 200 feats) for
// the same atoms -> serial contraction depth halved on this grid-limited
// kernel. Joint coalesced flush.
// ---------------------------------------------------------------------------
__global__ void __launch_bounds__(64) k_feat(float* __restrict__ outbuf) {
    __shared__ float shA[160 * 33];
    __shared__ float shB[200 * 33];

    int t = threadIdx.x;        // 0..63
    int lane = t & 31;
    int wrp = t >> 5;
    int a0 = blockIdx.x * 32;
    int a = a0 + lane;
    bool act = (a < NA);
    int nat = NA - a0;
    if (nat > 32) nat = 32;

    float A0[5] = {};
    float A1[5][3] = {};
    float A2[5][6] = {};
    float A3[5][10] = {};
    if (act) {
#pragma unroll
        for (int r = 0; r < 5; r++) A0[r] = __ldg(g_mom + r * NA + a);
#pragma unroll
        for (int r = 0; r < 5; r++)
#pragma unroll
            for (int u = 0; u < 3; u++) A1[r][u] = __ldg(g_mom + (5 + r * 3 + u) * NA + a);
#pragma unroll
        for (int r = 0; r < 5; r++)
#pragma unroll
            for (int u = 0; u < 6; u++) A2[r][u] = __ldg(g_mom + (20 + r * 6 + u) * NA + a);
#pragma unroll
        for (int r = 0; r < 5; r++)
#pragma unroll
            for (int u = 0; u < 10; u++) A3[r][u] = __ldg(g_mom + (50 + r * 10 + u) * NA + a);
    }

    if (wrp == 0) {
        // ---- chunk A: c0..c5 (160 features) ----
        int o = 0;
#define EMITA(v) do { if (act) shA[(o) * 33 + lane] = (v); o++; } while (0)
#pragma unroll
        for (int r = 0; r < 5; r++) EMITA(A0[r]);

#pragma unroll
        for (int r = 0; r < 5; r++)
#pragma unroll
            for (int s = 0; s <= r; s++) {
                float v = 0.f;
#pragma unroll
                for (int i = 0; i < 3; i++) v += A1[r][i] * A1[s][i];
                EMITA(v);
            }

        {
            const float W2[6] = {1.f, 2.f, 1.f, 2.f, 2.f, 1.f};
#pragma unroll
            for (int r = 0; r < 5; r++)
#pragma unroll
                for (int s = 0; s <= r; s++) {
                    float v = 0.f;
#pragma unroll
                    for (int u = 0; u < 6; u++) v += W2[u] * A2[r][u] * A2[s][u];
                    EMITA(v);
                }
        }

        {
            const float W3[10] = {1.f, 3.f, 3.f, 1.f, 3.f, 6.f, 3.f, 3.f, 3.f, 1.f};
#pragma unroll
            for (int r = 0; r < 5; r++)
#pragma unroll
                for (int s = 0; s <= r; s++) {
                    float v = 0.f;
#pragma unroll
                    for (int u = 0; u < 10; u++) v += W3[u] * A3[r][u] * A3[s][u];
                    EMITA(v);
                }
        }

        // c4
#pragma unroll
        for (int r = 0; r < 5; r++)
#pragma unroll
            for (int s = 0; s <= r; s++)
#pragma unroll
                for (int tt = 0; tt <= s; tt++) {
                    float v = 0.f;
#pragma unroll
                    for (int i = 0; i < 3; i++)
#pragma unroll
                        for (int j = 0; j < 3; j++)
#pragma unroll
                            for (int k = 0; k < 3; k++)
                                v += A2[r][s2i(i, j)] * A2[s][s2i(i, k)] * A2[tt][s2i(j, k)];
                    EMITA(v);
                }

        // c5
#pragma unroll
        for (int r = 0; r < 5; r++)
#pragma unroll
            for (int s = 0; s <= r; s++)
#pragma unroll
                for (int tt = 0; tt < 5; tt++) {
                    float v = 0.f;
#pragma unroll
                    for (int i = 0; i < 3; i++)
#pragma unroll
                        for (int j = 0; j < 3; j++)
                            v += A1[r][i] * A1[s][j] * A2[tt][s2i(i, j)];
                    EMITA(v);
                }
#undef EMITA
    } else {
        // ---- chunk B: c6, c7 (200 features) ----
        int o = 0;
#define EMITB(v) do { if (act) shB[(o) * 33 + lane] = (v); o++; } while (0)
#pragma unroll
        for (int r = 0; r < 5; r++)
#pragma unroll
            for (int s = 0; s <= r; s++) {
                float B[9];
#pragma unroll
                for (int k = 0; k < 3; k++)
#pragma unroll
                    for (int l = 0; l < 3; l++) {
                        float u = 0.f;
#pragma unroll
                        for (int i = 0; i < 3; i++)
#pragma unroll
                            for (int j = 0; j < 3; j++)
                                u += A3[r][s3i(i, j, k)] * A3[s][s3i(i, j, l)];
                        B[k * 3 + l] = u;
                    }
#pragma unroll
                for (int tt = 0; tt < 5; tt++) {
                    float v = 0.f;
#pragma unroll
                    for (int k = 0; k < 3; k++)
#pragma unroll
                        for (int l = 0; l < 3; l++)
                            v += B[k * 3 + l] * A2[tt][s2i(k, l)];
                    EMITB(v);
                }
            }

#pragma unroll
        for (int r = 0; r < 5; r++)
#pragma unroll
            for (int s = 0; s < 5; s++) {
                float C[3];
#pragma unroll
                for (int k = 0; k < 3; k++) {
                    float u = 0.f;
#pragma unroll
                    for (int i = 0; i < 3; i++)
#pragma unroll
                        for (int j = 0; j < 3; j++)
                            u += A3[r][s3i(i, j, k)] * A2[s][s2i(i, j)];
                    C[k] = u;
                }
#pragma unroll
                for (int tt = 0; tt < 5; tt++) {
                    float v = 0.f;
#pragma unroll
                    for (int k = 0; k < 3; k++) v += C[k] * A1[tt][k];
                    EMITB(v);
                }
            }
#undef EMITB
    }

    __syncthreads();

    // joint coalesced flush of all 360 features
    for (int idx = t; idx < nat * NFEAT; idx += 64) {
        int i = idx / NFEAT;
        int f = idx - i * NFEAT;
        float v = (f < 160) ? shA[f * 33 + i] : shB[(f - 160) * 33 + i];
        outbuf[(size_t)(a0 + i) * NFEAT + f] = v;
    }
}

extern "C" void kernel_launch(void* const* d_in, const int* in_sizes, int n_in,
                              void* d_out, int out_size) {
    const float* dr_vec = (const float*)d_in[0];
    const int*   Z      = (const int*)d_in[1];
    const int*   nbr    = (const int*)d_in[2];
    const float* emb    = (const float*)d_in[3];
    float*       out    = (float*)d_out;

    k_prep_hist<<<(NEMB + 255) / 256, 256>>>(emb, nbr, Z);
    k_scan2<<<2, 1024>>>();
    k_scatter<<<(NE + 255) / 256, 256>>>(dr_vec, nbr);
    k_edge<<<(NPAIR + 3) / 4, 128>>>();
    k_mom<<<(NA + 15) / 16, 128>>>();
    k_feat<<<(NA + 31) / 32, 64>>>(out);
}